// round 3
// baseline (speedup 1.0000x reference)
#include <cuda_runtime.h>
#include <cuda_bf16.h>
#include <cstdint>

#define KDIM 256
#define ODIM 64
#define MAX_NODES 50048
#define MAX_E 1664000
#define SW_STRIDE 72  // 64 + 8 pad: conflict-free B LDS

// -------- device scratch (static — no allocation) --------
__device__ float g_support[(size_t)MAX_NODES * ODIM];   // 12.8 MB
__device__ int   g_count[MAX_NODES + 1];
__device__ int   g_offset[MAX_NODES + 1];
__device__ int   g_cursor[MAX_NODES + 1];
__device__ int2  g_edges[MAX_E];                        // packed (col, weight-bits)

__device__ __forceinline__ uint32_t f2tf32(float x) {
    uint32_t r;
    asm("cvt.rna.tf32.f32 %0, %1;" : "=r"(r) : "f"(x));
    return r;
}

// ---------------------------------------------------------------------------
// tf32 tensor-core GEMM: support[n,64] = F[n,256] @ W[256,64]
// ---------------------------------------------------------------------------
__global__ __launch_bounds__(256) void gnn_gemm_tf32(const float* __restrict__ F,
                                                     const float* __restrict__ W,
                                                     int nrows) {
    __shared__ uint32_t sw[128 * SW_STRIDE];  // 36 KB

    const int tid  = threadIdx.x;
    const int warp = tid >> 5;
    const int lane = tid & 31;
    const int g    = lane >> 2;
    const int tig  = lane & 3;

    const int rowbase = blockIdx.x * 128 + warp * 16;
    const int r0 = rowbase + g;
    const int r1 = rowbase + g + 8;
    const int r0c = r0 < nrows ? r0 : nrows - 1;
    const int r1c = r1 < nrows ? r1 : nrows - 1;
    const float* F0 = F + (size_t)r0c * KDIM;
    const float* F1 = F + (size_t)r1c * KDIM;

    float acc[8][4];
#pragma unroll
    for (int nt = 0; nt < 8; ++nt)
#pragma unroll
        for (int i = 0; i < 4; ++i) acc[nt][i] = 0.f;

    for (int pass = 0; pass < 2; ++pass) {
        const float4* src = reinterpret_cast<const float4*>(W + pass * 128 * ODIM);
#pragma unroll
        for (int i = tid; i < 128 * 16; i += 256) {
            float4 v = src[i];
            int krow = i >> 4;
            int nc = (i & 15) * 4;
            uint32_t* d = &sw[krow * SW_STRIDE + nc];
            d[0] = f2tf32(v.x);
            d[1] = f2tf32(v.y);
            d[2] = f2tf32(v.z);
            d[3] = f2tf32(v.w);
        }
        __syncthreads();

        const int kglob = pass * 128;
#pragma unroll 4
        for (int ks = 0; ks < 128; ks += 8) {
            uint32_t a0 = f2tf32(F0[kglob + ks + tig]);
            uint32_t a1 = f2tf32(F1[kglob + ks + tig]);
            uint32_t a2 = f2tf32(F0[kglob + ks + tig + 4]);
            uint32_t a3 = f2tf32(F1[kglob + ks + tig + 4]);
#pragma unroll
            for (int nt = 0; nt < 8; ++nt) {
                uint32_t b0 = sw[(ks + tig) * SW_STRIDE + nt * 8 + g];
                uint32_t b1 = sw[(ks + tig + 4) * SW_STRIDE + nt * 8 + g];
                asm("mma.sync.aligned.m16n8k8.row.col.f32.tf32.tf32.f32 "
                    "{%0,%1,%2,%3}, {%4,%5,%6,%7}, {%8,%9}, {%0,%1,%2,%3};"
                    : "+f"(acc[nt][0]), "+f"(acc[nt][1]),
                      "+f"(acc[nt][2]), "+f"(acc[nt][3])
                    : "r"(a0), "r"(a1), "r"(a2), "r"(a3), "r"(b0), "r"(b1));
            }
        }
        __syncthreads();
    }

    if (r0 < nrows) {
        float* dst = g_support + (size_t)r0 * ODIM;
#pragma unroll
        for (int nt = 0; nt < 8; ++nt)
            *reinterpret_cast<float2*>(dst + nt * 8 + tig * 2) =
                make_float2(acc[nt][0], acc[nt][1]);
    }
    if (r1 < nrows) {
        float* dst = g_support + (size_t)r1 * ODIM;
#pragma unroll
        for (int nt = 0; nt < 8; ++nt)
            *reinterpret_cast<float2*>(dst + nt * 8 + tig * 2) =
                make_float2(acc[nt][2], acc[nt][3]);
    }
}

// ---------------------------------------------------------------------------
// Edge sort pipeline: counting sort by destination row.
// ---------------------------------------------------------------------------
__global__ void zero_counts(int n) {
    int i = blockIdx.x * blockDim.x + threadIdx.x;
    if (i <= n) g_count[i] = 0;
}

__global__ void histogram_kernel(const int* __restrict__ erow, int E) {
    int e = blockIdx.x * blockDim.x + threadIdx.x;
    if (e < E) atomicAdd(&g_count[erow[e]], 1);
}

// Single-block exclusive scan over g_count[0..n) -> g_offset / g_cursor.
__global__ __launch_bounds__(1024) void scan_kernel(int n) {
    __shared__ int part[1024];
    const int tid = threadIdx.x;
    const int CH = (n + 1023) / 1024;
    const int beg = tid * CH;
    const int end = min(beg + CH, n);

    int s = 0;
    for (int i = beg; i < end; ++i) s += g_count[i];
    part[tid] = s;
    __syncthreads();

    // Hillis–Steele inclusive scan on partials
    for (int d = 1; d < 1024; d <<= 1) {
        int v = (tid >= d) ? part[tid - d] : 0;
        __syncthreads();
        part[tid] += v;
        __syncthreads();
    }

    int base = (tid == 0) ? 0 : part[tid - 1];
    for (int i = beg; i < end; ++i) {
        g_offset[i] = base;
        g_cursor[i] = base;
        base += g_count[i];
    }
    if (tid == 1023) g_offset[n] = part[1023];
}

__global__ void sort_scatter_kernel(const int* __restrict__ erow,
                                    const int* __restrict__ ecol,
                                    const float* __restrict__ ew,
                                    int E) {
    int e = blockIdx.x * blockDim.x + threadIdx.x;
    if (e >= E) return;
    int r = erow[e];
    int pos = atomicAdd(&g_cursor[r], 1);
    g_edges[pos] = make_int2(ecol[e], __float_as_int(ew[e]));
}

// ---------------------------------------------------------------------------
// CSR SpMM + fused tanh: warp per destination row, 2 edges in flight
// (half-warps), 16 lanes x float4 cover 64 cols. Single coalesced write.
// ---------------------------------------------------------------------------
__global__ __launch_bounds__(256) void csr_spmm_kernel(float* __restrict__ out,
                                                       const int* __restrict__ act,
                                                       int nrows) {
    int wid = (blockIdx.x * blockDim.x + threadIdx.x) >> 5;
    if (wid >= nrows) return;
    const int lane = threadIdx.x & 31;
    const int h = lane >> 4;          // edge slot 0/1
    const int j = (lane & 15) * 4;    // column offset

    const int beg = g_offset[wid];
    const int end = g_offset[wid + 1];

    float4 acc = make_float4(0.f, 0.f, 0.f, 0.f);
    for (int e = beg + h; e < end; e += 2) {
        int2 cw = g_edges[e];
        float w = __int_as_float(cw.y);
        float4 v = *reinterpret_cast<const float4*>(
            g_support + (size_t)cw.x * ODIM + j);
        acc.x += v.x * w;
        acc.y += v.y * w;
        acc.z += v.z * w;
        acc.w += v.w * w;
    }

    // fold slot 1 into slot 0
    acc.x += __shfl_down_sync(0xFFFFFFFF, acc.x, 16);
    acc.y += __shfl_down_sync(0xFFFFFFFF, acc.y, 16);
    acc.z += __shfl_down_sync(0xFFFFFFFF, acc.z, 16);
    acc.w += __shfl_down_sync(0xFFFFFFFF, acc.w, 16);

    if (h == 0) {
        if (*act) {
            acc.x = tanhf(acc.x);
            acc.y = tanhf(acc.y);
            acc.z = tanhf(acc.z);
            acc.w = tanhf(acc.w);
        }
        *reinterpret_cast<float4*>(out + (size_t)wid * ODIM + j) = acc;
    }
}

extern "C" void kernel_launch(void* const* d_in, const int* in_sizes, int n_in,
                              void* d_out, int out_size) {
    const float* F   = (const float*)d_in[0];
    const float* W   = (const float*)d_in[1];
    const int*   er  = (const int*)d_in[2];
    const int*   ec  = (const int*)d_in[3];
    const float* ew  = (const float*)d_in[4];
    const int*   act = (const int*)d_in[5];

    int nrows = in_sizes[0] / KDIM;
    int E = in_sizes[2];
    float* out = (float*)d_out;

    // 1) dense projection (tf32 tensor cores)
    gnn_gemm_tf32<<<(nrows + 127) / 128, 256>>>(F, W, nrows);

    // 2) counting sort of edges by destination row
    zero_counts<<<(nrows + 256) / 256, 256>>>(nrows);
    histogram_kernel<<<(E + 255) / 256, 256>>>(er, E);
    scan_kernel<<<1, 1024>>>(nrows);
    sort_scatter_kernel<<<(E + 255) / 256, 256>>>(er, ec, ew, E);

    // 3) CSR SpMM with fused zero-init + tanh (warp per row)
    int warps = nrows;
    int blocks = (warps * 32 + 255) / 256;
    csr_spmm_kernel<<<blocks, 256>>>(out, act, nrows);
}

// round 4
// speedup vs baseline: 1.4917x; 1.4917x over previous
#include <cuda_runtime.h>
#include <cuda_bf16.h>
#include <cstdint>

#define KDIM 256
#define ODIM 64
#define MAX_NODES 50048
#define MAX_E 1664000
#define SW_STRIDE 72  // 64 + 8 pad: conflict-free B LDS
#define SCAN_BLK 1024
#define MAX_SCAN_BLOCKS 64

// -------- device scratch (static — no allocation) --------
__device__ float g_support[(size_t)MAX_NODES * ODIM];   // 12.8 MB
__device__ int   g_count[MAX_NODES + 1];
__device__ int   g_offset[MAX_NODES + 1];
__device__ int   g_cursor[MAX_NODES + 1];
__device__ int   g_bsum[MAX_SCAN_BLOCKS];
__device__ int   g_bbase[MAX_SCAN_BLOCKS];
__device__ int2  g_edges[MAX_E];                        // packed (col, weight-bits)

__device__ __forceinline__ uint32_t f2tf32(float x) {
    uint32_t r;
    asm("cvt.rna.tf32.f32 %0, %1;" : "=r"(r) : "f"(x));
    return r;
}

// ---------------------------------------------------------------------------
// tf32 tensor-core GEMM: support[n,64] = F[n,256] @ W[256,64]
// 512 threads (16 warps), tile 128 rows x 64 cols.
// Warp w: rows [(w&7)*16, +16), cols [(w>>3)*32, +32)  -> 4 m16n8 acc tiles.
// ---------------------------------------------------------------------------
__global__ __launch_bounds__(512) void gnn_gemm_tf32(const float* __restrict__ F,
                                                     const float* __restrict__ W,
                                                     int nrows) {
    __shared__ uint32_t sw[128 * SW_STRIDE];  // 36 KB

    const int tid  = threadIdx.x;
    const int warp = tid >> 5;
    const int lane = tid & 31;
    const int g    = lane >> 2;
    const int tig  = lane & 3;
    const int cbase = (warp >> 3) * 32;   // column half

    const int rowbase = blockIdx.x * 128 + (warp & 7) * 16;
    const int r0 = rowbase + g;
    const int r1 = rowbase + g + 8;
    const int r0c = r0 < nrows ? r0 : nrows - 1;
    const int r1c = r1 < nrows ? r1 : nrows - 1;
    const float* F0 = F + (size_t)r0c * KDIM;
    const float* F1 = F + (size_t)r1c * KDIM;

    float acc[4][4];
#pragma unroll
    for (int nt = 0; nt < 4; ++nt)
#pragma unroll
        for (int i = 0; i < 4; ++i) acc[nt][i] = 0.f;

    for (int pass = 0; pass < 2; ++pass) {
        const float4* src = reinterpret_cast<const float4*>(W + pass * 128 * ODIM);
#pragma unroll
        for (int i = tid; i < 128 * 16; i += 512) {
            float4 v = src[i];
            int krow = i >> 4;
            int nc = (i & 15) * 4;
            uint32_t* d = &sw[krow * SW_STRIDE + nc];
            d[0] = f2tf32(v.x);
            d[1] = f2tf32(v.y);
            d[2] = f2tf32(v.z);
            d[3] = f2tf32(v.w);
        }
        __syncthreads();

        const int kglob = pass * 128;
#pragma unroll 4
        for (int ks = 0; ks < 128; ks += 8) {
            uint32_t a0 = f2tf32(F0[kglob + ks + tig]);
            uint32_t a1 = f2tf32(F1[kglob + ks + tig]);
            uint32_t a2 = f2tf32(F0[kglob + ks + tig + 4]);
            uint32_t a3 = f2tf32(F1[kglob + ks + tig + 4]);
#pragma unroll
            for (int nt = 0; nt < 4; ++nt) {
                uint32_t b0 = sw[(ks + tig) * SW_STRIDE + cbase + nt * 8 + g];
                uint32_t b1 = sw[(ks + tig + 4) * SW_STRIDE + cbase + nt * 8 + g];
                asm("mma.sync.aligned.m16n8k8.row.col.f32.tf32.tf32.f32 "
                    "{%0,%1,%2,%3}, {%4,%5,%6,%7}, {%8,%9}, {%0,%1,%2,%3};"
                    : "+f"(acc[nt][0]), "+f"(acc[nt][1]),
                      "+f"(acc[nt][2]), "+f"(acc[nt][3])
                    : "r"(a0), "r"(a1), "r"(a2), "r"(a3), "r"(b0), "r"(b1));
            }
        }
        __syncthreads();
    }

    if (r0 < nrows) {
        float* dst = g_support + (size_t)r0 * ODIM + cbase;
#pragma unroll
        for (int nt = 0; nt < 4; ++nt)
            *reinterpret_cast<float2*>(dst + nt * 8 + tig * 2) =
                make_float2(acc[nt][0], acc[nt][1]);
    }
    if (r1 < nrows) {
        float* dst = g_support + (size_t)r1 * ODIM + cbase;
#pragma unroll
        for (int nt = 0; nt < 4; ++nt)
            *reinterpret_cast<float2*>(dst + nt * 8 + tig * 2) =
                make_float2(acc[nt][2], acc[nt][3]);
    }
}

// ---------------------------------------------------------------------------
// Edge counting-sort pipeline
// ---------------------------------------------------------------------------
__global__ void zero_counts(int n) {
    int i = blockIdx.x * blockDim.x + threadIdx.x;
    if (i <= n) g_count[i] = 0;
}

__global__ void histogram_kernel(const int* __restrict__ erow, int E) {
    int e = blockIdx.x * blockDim.x + threadIdx.x;
    if (e < E) atomicAdd(&g_count[erow[e]], 1);
}

// Stage 1: per-block (1024-wide) exclusive scan via warp shuffles.
__global__ __launch_bounds__(SCAN_BLK) void scan_blocks(int n) {
    __shared__ int wsum[32];
    const int t = threadIdx.x;
    const int i = blockIdx.x * SCAN_BLK + t;
    int v = (i < n) ? g_count[i] : 0;

    int x = v;
#pragma unroll
    for (int d = 1; d < 32; d <<= 1) {
        int y = __shfl_up_sync(0xFFFFFFFF, x, d);
        if ((t & 31) >= d) x += y;
    }
    if ((t & 31) == 31) wsum[t >> 5] = x;
    __syncthreads();
    if (t < 32) {
        int s = wsum[t];
#pragma unroll
        for (int d = 1; d < 32; d <<= 1) {
            int y = __shfl_up_sync(0xFFFFFFFF, s, d);
            if (t >= d) s += y;
        }
        wsum[t] = s;
    }
    __syncthreads();
    int base = (t >= 32) ? wsum[(t >> 5) - 1] : 0;
    int incl = x + base;
    if (i < n) g_offset[i] = incl - v;  // block-local exclusive
    if (t == SCAN_BLK - 1) g_bsum[blockIdx.x] = incl;
}

// Stage 2: scan the (<=64) block sums; also publish the grand total.
__global__ void scan_top(int nblocks, int n) {
    __shared__ int s[MAX_SCAN_BLOCKS];
    int t = threadIdx.x;
    s[t] = (t < nblocks) ? g_bsum[t] : 0;
    __syncthreads();
#pragma unroll
    for (int d = 1; d < MAX_SCAN_BLOCKS; d <<= 1) {
        int y = (t >= d) ? s[t - d] : 0;
        __syncthreads();
        s[t] += y;
        __syncthreads();
    }
    if (t < nblocks) g_bbase[t] = (t == 0) ? 0 : s[t - 1];
    if (t == MAX_SCAN_BLOCKS - 1) g_offset[n] = s[MAX_SCAN_BLOCKS - 1];
}

// Stage 3: add block bases, mirror into cursor.
__global__ void scan_apply(int n) {
    int i = blockIdx.x * blockDim.x + threadIdx.x;
    if (i < n) {
        int v = g_offset[i] + g_bbase[i >> 10];
        g_offset[i] = v;
        g_cursor[i] = v;
    }
}

__global__ void sort_scatter_kernel(const int* __restrict__ erow,
                                    const int* __restrict__ ecol,
                                    const float* __restrict__ ew,
                                    int E) {
    int e = blockIdx.x * blockDim.x + threadIdx.x;
    if (e >= E) return;
    int r = erow[e];
    int pos = atomicAdd(&g_cursor[r], 1);
    g_edges[pos] = make_int2(ecol[e], __float_as_int(ew[e]));
}

// ---------------------------------------------------------------------------
// CSR SpMM + fused zero-init + tanh: warp per destination row.
// ---------------------------------------------------------------------------
__global__ __launch_bounds__(256) void csr_spmm_kernel(float* __restrict__ out,
                                                       const int* __restrict__ act,
                                                       int nrows) {
    int wid = (blockIdx.x * blockDim.x + threadIdx.x) >> 5;
    if (wid >= nrows) return;
    const int lane = threadIdx.x & 31;
    const int h = lane >> 4;
    const int j = (lane & 15) * 4;

    const int beg = g_offset[wid];
    const int end = g_offset[wid + 1];

    float4 acc = make_float4(0.f, 0.f, 0.f, 0.f);
    for (int e = beg + h; e < end; e += 2) {
        int2 cw = g_edges[e];
        float w = __int_as_float(cw.y);
        float4 v = *reinterpret_cast<const float4*>(
            g_support + (size_t)cw.x * ODIM + j);
        acc.x += v.x * w;
        acc.y += v.y * w;
        acc.z += v.z * w;
        acc.w += v.w * w;
    }

    acc.x += __shfl_down_sync(0xFFFFFFFF, acc.x, 16);
    acc.y += __shfl_down_sync(0xFFFFFFFF, acc.y, 16);
    acc.z += __shfl_down_sync(0xFFFFFFFF, acc.z, 16);
    acc.w += __shfl_down_sync(0xFFFFFFFF, acc.w, 16);

    if (h == 0) {
        if (*act) {
            acc.x = tanhf(acc.x);
            acc.y = tanhf(acc.y);
            acc.z = tanhf(acc.z);
            acc.w = tanhf(acc.w);
        }
        *reinterpret_cast<float4*>(out + (size_t)wid * ODIM + j) = acc;
    }
}

extern "C" void kernel_launch(void* const* d_in, const int* in_sizes, int n_in,
                              void* d_out, int out_size) {
    const float* F   = (const float*)d_in[0];
    const float* W   = (const float*)d_in[1];
    const int*   er  = (const int*)d_in[2];
    const int*   ec  = (const int*)d_in[3];
    const float* ew  = (const float*)d_in[4];
    const int*   act = (const int*)d_in[5];

    int nrows = in_sizes[0] / KDIM;
    int E = in_sizes[2];
    float* out = (float*)d_out;

    // 1) dense projection (tf32 tensor cores, 16 warps/block)
    gnn_gemm_tf32<<<(nrows + 127) / 128, 512>>>(F, W, nrows);

    // 2) counting sort of edges by destination row (hierarchical scan)
    int nsb = (nrows + SCAN_BLK - 1) / SCAN_BLK;  // <= 64
    zero_counts<<<(nrows + 256) / 256, 256>>>(nrows);
    histogram_kernel<<<(E + 255) / 256, 256>>>(er, E);
    scan_blocks<<<nsb, SCAN_BLK>>>(nrows);
    scan_top<<<1, MAX_SCAN_BLOCKS>>>(nsb, nrows);
    scan_apply<<<(nrows + 255) / 256, 256>>>(nrows);
    sort_scatter_kernel<<<(E + 255) / 256, 256>>>(er, ec, ew, E);

    // 3) CSR SpMM with fused zero-init + tanh (warp per row)
    int blocks = (nrows * 32 + 255) / 256;
    csr_spmm_kernel<<<blocks, 256>>>(out, act, nrows);
}

// round 5
// speedup vs baseline: 1.6125x; 1.0810x over previous
#include <cuda_runtime.h>
#include <cuda_bf16.h>
#include <cstdint>

#define KDIM 256
#define ODIM 64
#define MAX_NODES 50048
#define MAX_E 1664000
#define SW_STRIDE 72  // 64 + 8 pad: conflict-free B LDS
#define SCAN_BLK 1024
#define MAX_SCAN_BLOCKS 64

// -------- device scratch (static — no allocation) --------
__device__ float g_support[(size_t)MAX_NODES * ODIM];   // 12.8 MB
__device__ int   g_count[MAX_NODES + 1];
__device__ int   g_offset[MAX_NODES + 1];
__device__ int   g_cursor[MAX_NODES + 1];
__device__ int   g_bsum[MAX_SCAN_BLOCKS];
__device__ int   g_bbase[MAX_SCAN_BLOCKS];
__device__ int2  g_edges[MAX_E];                        // packed (col, weight-bits)

__device__ __forceinline__ uint32_t f2tf32(float x) {
    uint32_t r;
    asm("cvt.rna.tf32.f32 %0, %1;" : "=r"(r) : "f"(x));
    return r;
}

// ---------------------------------------------------------------------------
// tf32 tensor-core GEMM: support[n,64] = F[n,256] @ W[256,64]
// 512 threads (16 warps); warp w: rows [(w&7)*16,+16), cols [(w>>3)*32,+32).
// ---------------------------------------------------------------------------
__global__ __launch_bounds__(512) void gnn_gemm_tf32(const float* __restrict__ F,
                                                     const float* __restrict__ W,
                                                     int nrows) {
    __shared__ uint32_t sw[128 * SW_STRIDE];  // 36 KB

    const int tid  = threadIdx.x;
    const int warp = tid >> 5;
    const int lane = tid & 31;
    const int g    = lane >> 2;
    const int tig  = lane & 3;
    const int cbase = (warp >> 3) * 32;

    const int rowbase = blockIdx.x * 128 + (warp & 7) * 16;
    const int r0 = rowbase + g;
    const int r1 = rowbase + g + 8;
    const int r0c = r0 < nrows ? r0 : nrows - 1;
    const int r1c = r1 < nrows ? r1 : nrows - 1;
    const float* F0 = F + (size_t)r0c * KDIM;
    const float* F1 = F + (size_t)r1c * KDIM;

    float acc[4][4];
#pragma unroll
    for (int nt = 0; nt < 4; ++nt)
#pragma unroll
        for (int i = 0; i < 4; ++i) acc[nt][i] = 0.f;

    for (int pass = 0; pass < 2; ++pass) {
        const float4* src = reinterpret_cast<const float4*>(W + pass * 128 * ODIM);
#pragma unroll
        for (int i = tid; i < 128 * 16; i += 512) {
            float4 v = src[i];
            int krow = i >> 4;
            int nc = (i & 15) * 4;
            uint32_t* d = &sw[krow * SW_STRIDE + nc];
            d[0] = f2tf32(v.x);
            d[1] = f2tf32(v.y);
            d[2] = f2tf32(v.z);
            d[3] = f2tf32(v.w);
        }
        __syncthreads();

        const int kglob = pass * 128;
#pragma unroll 4
        for (int ks = 0; ks < 128; ks += 8) {
            uint32_t a0 = f2tf32(F0[kglob + ks + tig]);
            uint32_t a1 = f2tf32(F1[kglob + ks + tig]);
            uint32_t a2 = f2tf32(F0[kglob + ks + tig + 4]);
            uint32_t a3 = f2tf32(F1[kglob + ks + tig + 4]);
#pragma unroll
            for (int nt = 0; nt < 4; ++nt) {
                uint32_t b0 = sw[(ks + tig) * SW_STRIDE + cbase + nt * 8 + g];
                uint32_t b1 = sw[(ks + tig + 4) * SW_STRIDE + cbase + nt * 8 + g];
                asm("mma.sync.aligned.m16n8k8.row.col.f32.tf32.tf32.f32 "
                    "{%0,%1,%2,%3}, {%4,%5,%6,%7}, {%8,%9}, {%0,%1,%2,%3};"
                    : "+f"(acc[nt][0]), "+f"(acc[nt][1]),
                      "+f"(acc[nt][2]), "+f"(acc[nt][3])
                    : "r"(a0), "r"(a1), "r"(a2), "r"(a3), "r"(b0), "r"(b1));
            }
        }
        __syncthreads();
    }

    if (r0 < nrows) {
        float* dst = g_support + (size_t)r0 * ODIM + cbase;
#pragma unroll
        for (int nt = 0; nt < 4; ++nt)
            *reinterpret_cast<float2*>(dst + nt * 8 + tig * 2) =
                make_float2(acc[nt][0], acc[nt][1]);
    }
    if (r1 < nrows) {
        float* dst = g_support + (size_t)r1 * ODIM + cbase;
#pragma unroll
        for (int nt = 0; nt < 4; ++nt)
            *reinterpret_cast<float2*>(dst + nt * 8 + tig * 2) =
                make_float2(acc[nt][2], acc[nt][3]);
    }
}

// ---------------------------------------------------------------------------
// Edge counting-sort pipeline
// ---------------------------------------------------------------------------
__global__ void zero_counts(int n) {
    int i = blockIdx.x * blockDim.x + threadIdx.x;
    if (i <= n) g_count[i] = 0;
}

__global__ void histogram_kernel(const int* __restrict__ erow, int E) {
    int e = blockIdx.x * blockDim.x + threadIdx.x;
    if (e < E) atomicAdd(&g_count[erow[e]], 1);
}

__global__ __launch_bounds__(SCAN_BLK) void scan_blocks(int n) {
    __shared__ int wsum[32];
    const int t = threadIdx.x;
    const int i = blockIdx.x * SCAN_BLK + t;
    int v = (i < n) ? g_count[i] : 0;

    int x = v;
#pragma unroll
    for (int d = 1; d < 32; d <<= 1) {
        int y = __shfl_up_sync(0xFFFFFFFF, x, d);
        if ((t & 31) >= d) x += y;
    }
    if ((t & 31) == 31) wsum[t >> 5] = x;
    __syncthreads();
    if (t < 32) {
        int s = wsum[t];
#pragma unroll
        for (int d = 1; d < 32; d <<= 1) {
            int y = __shfl_up_sync(0xFFFFFFFF, s, d);
            if (t >= d) s += y;
        }
        wsum[t] = s;
    }
    __syncthreads();
    int base = (t >= 32) ? wsum[(t >> 5) - 1] : 0;
    int incl = x + base;
    if (i < n) g_offset[i] = incl - v;  // block-local exclusive
    if (t == SCAN_BLK - 1) g_bsum[blockIdx.x] = incl;
}

__global__ void scan_top(int nblocks, int n) {
    __shared__ int s[MAX_SCAN_BLOCKS];
    int t = threadIdx.x;
    s[t] = (t < nblocks) ? g_bsum[t] : 0;
    __syncthreads();
#pragma unroll
    for (int d = 1; d < MAX_SCAN_BLOCKS; d <<= 1) {
        int y = (t >= d) ? s[t - d] : 0;
        __syncthreads();
        s[t] += y;
        __syncthreads();
    }
    if (t < nblocks) g_bbase[t] = (t == 0) ? 0 : s[t - 1];
    if (t == MAX_SCAN_BLOCKS - 1) g_offset[n] = s[MAX_SCAN_BLOCKS - 1];
}

__global__ void scan_apply(int n) {
    int i = blockIdx.x * blockDim.x + threadIdx.x;
    if (i < n) {
        int v = g_offset[i] + g_bbase[i >> 10];
        g_offset[i] = v;
        g_cursor[i] = v;
    }
}

__global__ void sort_scatter_kernel(const int* __restrict__ erow,
                                    const int* __restrict__ ecol,
                                    const float* __restrict__ ew,
                                    int E) {
    int e = blockIdx.x * blockDim.x + threadIdx.x;
    if (e >= E) return;
    int r = erow[e];
    int pos = atomicAdd(&g_cursor[r], 1);
    g_edges[pos] = make_int2(ecol[e], __float_as_int(ew[e]));
}

// ---------------------------------------------------------------------------
// CSR SpMM + fused zero-init + tanh: warp per destination row.
// Half-warp per edge slot, 2-deep unroll -> up to 2 gathers in flight / lane.
// ---------------------------------------------------------------------------
__global__ __launch_bounds__(256) void csr_spmm_kernel(float* __restrict__ out,
                                                       const int* __restrict__ act,
                                                       int nrows) {
    int wid = (blockIdx.x * blockDim.x + threadIdx.x) >> 5;
    if (wid >= nrows) return;
    const int lane = threadIdx.x & 31;
    const int h = lane >> 4;
    const int j = (lane & 15) * 4;

    const int beg = g_offset[wid];
    const int end = g_offset[wid + 1];

    float4 acc  = make_float4(0.f, 0.f, 0.f, 0.f);
    float4 acc2 = make_float4(0.f, 0.f, 0.f, 0.f);

    int e = beg + h;
    for (; e + 2 < end; e += 4) {
        int2 cw0 = g_edges[e];
        int2 cw1 = g_edges[e + 2];
        float4 v0 = *reinterpret_cast<const float4*>(
            g_support + (size_t)cw0.x * ODIM + j);
        float4 v1 = *reinterpret_cast<const float4*>(
            g_support + (size_t)cw1.x * ODIM + j);
        float w0 = __int_as_float(cw0.y);
        float w1 = __int_as_float(cw1.y);
        acc.x += v0.x * w0;  acc.y += v0.y * w0;
        acc.z += v0.z * w0;  acc.w += v0.w * w0;
        acc2.x += v1.x * w1; acc2.y += v1.y * w1;
        acc2.z += v1.z * w1; acc2.w += v1.w * w1;
    }
    if (e < end) {
        int2 cw = g_edges[e];
        float w = __int_as_float(cw.y);
        float4 v = *reinterpret_cast<const float4*>(
            g_support + (size_t)cw.x * ODIM + j);
        acc.x += v.x * w; acc.y += v.y * w;
        acc.z += v.z * w; acc.w += v.w * w;
    }
    acc.x += acc2.x; acc.y += acc2.y; acc.z += acc2.z; acc.w += acc2.w;

    acc.x += __shfl_down_sync(0xFFFFFFFF, acc.x, 16);
    acc.y += __shfl_down_sync(0xFFFFFFFF, acc.y, 16);
    acc.z += __shfl_down_sync(0xFFFFFFFF, acc.z, 16);
    acc.w += __shfl_down_sync(0xFFFFFFFF, acc.w, 16);

    if (h == 0) {
        if (*act) {
            acc.x = tanhf(acc.x);
            acc.y = tanhf(acc.y);
            acc.z = tanhf(acc.z);
            acc.w = tanhf(acc.w);
        }
        *reinterpret_cast<float4*>(out + (size_t)wid * ODIM + j) = acc;
    }
}

extern "C" void kernel_launch(void* const* d_in, const int* in_sizes, int n_in,
                              void* d_out, int out_size) {
    const float* F   = (const float*)d_in[0];
    const float* W   = (const float*)d_in[1];
    const int*   er  = (const int*)d_in[2];
    const int*   ec  = (const int*)d_in[3];
    const float* ew  = (const float*)d_in[4];
    const int*   act = (const int*)d_in[5];

    int nrows = in_sizes[0] / KDIM;
    int E = in_sizes[2];
    float* out = (float*)d_out;

    // One-time infra (first call is the non-captured correctness run).
    static cudaStream_t s2 = nullptr;
    static cudaEvent_t evFork = nullptr, evJoin = nullptr;
    if (s2 == nullptr) {
        cudaStreamCreateWithFlags(&s2, cudaStreamNonBlocking);
        cudaEventCreateWithFlags(&evFork, cudaEventDisableTiming);
        cudaEventCreateWithFlags(&evJoin, cudaEventDisableTiming);
    }

    // Fork: branch B (edge sort) on s2, branch A (GEMM) on stream 0.
    cudaEventRecord(evFork, 0);
    cudaStreamWaitEvent(s2, evFork, 0);

    // Branch B: counting sort of edges by destination row.
    int nsb = (nrows + SCAN_BLK - 1) / SCAN_BLK;  // <= 64
    zero_counts<<<(nrows + 256) / 256, 256, 0, s2>>>(nrows);
    histogram_kernel<<<(E + 255) / 256, 256, 0, s2>>>(er, E);
    scan_blocks<<<nsb, SCAN_BLK, 0, s2>>>(nrows);
    scan_top<<<1, MAX_SCAN_BLOCKS, 0, s2>>>(nsb, nrows);
    scan_apply<<<(nrows + 255) / 256, 256, 0, s2>>>(nrows);
    sort_scatter_kernel<<<(E + 255) / 256, 256, 0, s2>>>(er, ec, ew, E);

    // Branch A: dense projection (tf32 tensor cores).
    gnn_gemm_tf32<<<(nrows + 127) / 128, 512>>>(F, W, nrows);

    // Join.
    cudaEventRecord(evJoin, s2);
    cudaStreamWaitEvent(0, evJoin, 0);

    // CSR SpMM with fused zero-init + tanh (warp per row).
    int blocks = (nrows * 32 + 255) / 256;
    csr_spmm_kernel<<<blocks, 256>>>(out, act, nrows);
}

// round 7
// speedup vs baseline: 1.6894x; 1.0477x over previous
#include <cuda_runtime.h>
#include <cuda_bf16.h>
#include <cstdint>

#define KDIM 256
#define ODIM 64
#define MAX_NODES 50048
#define MAX_E 1664000
#define SW_STRIDE 72  // 64 + 8 pad: conflict-free B LDS
#define SCAN_BLK 1024
#define MAX_SCAN_BLOCKS 64

// -------- device scratch (static — no allocation; zero-initialized) --------
__device__ float g_support[(size_t)MAX_NODES * ODIM];   // 12.8 MB
__device__ int   g_count[MAX_NODES + 1];                // zeroed by csr_spmm tail
__device__ int   g_offset[MAX_NODES + 1];
__device__ int   g_cursor[MAX_NODES + 1];
__device__ int   g_aggr[MAX_SCAN_BLOCKS];
__device__ volatile int g_flag[MAX_SCAN_BLOCKS];        // zeroed by csr_spmm tail
__device__ int2  g_edges[MAX_E];                        // packed (col, weight-bits)

__device__ __forceinline__ uint32_t f2tf32(float x) {
    uint32_t r;
    asm("cvt.rna.tf32.f32 %0, %1;" : "=r"(r) : "f"(x));
    return r;
}

// ---------------------------------------------------------------------------
// tf32 tensor-core GEMM: support[n,64] = F[n,256] @ W[256,64]
// 512 threads (16 warps); warp w: rows [(w&7)*16,+16), cols [(w>>3)*32,+32).
// ---------------------------------------------------------------------------
__global__ __launch_bounds__(512) void gnn_gemm_tf32(const float* __restrict__ F,
                                                     const float* __restrict__ W,
                                                     int nrows) {
    __shared__ uint32_t sw[128 * SW_STRIDE];  // 36 KB

    const int tid  = threadIdx.x;
    const int warp = tid >> 5;
    const int lane = tid & 31;
    const int g    = lane >> 2;
    const int tig  = lane & 3;
    const int cbase = (warp >> 3) * 32;

    const int rowbase = blockIdx.x * 128 + (warp & 7) * 16;
    const int r0 = rowbase + g;
    const int r1 = rowbase + g + 8;
    const int r0c = r0 < nrows ? r0 : nrows - 1;
    const int r1c = r1 < nrows ? r1 : nrows - 1;
    const float* F0 = F + (size_t)r0c * KDIM;
    const float* F1 = F + (size_t)r1c * KDIM;

    float acc[4][4];
#pragma unroll
    for (int nt = 0; nt < 4; ++nt)
#pragma unroll
        for (int i = 0; i < 4; ++i) acc[nt][i] = 0.f;

    for (int pass = 0; pass < 2; ++pass) {
        const float4* src = reinterpret_cast<const float4*>(W + pass * 128 * ODIM);
#pragma unroll
        for (int i = tid; i < 128 * 16; i += 512) {
            float4 v = src[i];
            int krow = i >> 4;
            int nc = (i & 15) * 4;
            uint32_t* d = &sw[krow * SW_STRIDE + nc];
            d[0] = f2tf32(v.x);
            d[1] = f2tf32(v.y);
            d[2] = f2tf32(v.z);
            d[3] = f2tf32(v.w);
        }
        __syncthreads();

        const int kglob = pass * 128;
#pragma unroll 4
        for (int ks = 0; ks < 128; ks += 8) {
            uint32_t a0 = f2tf32(F0[kglob + ks + tig]);
            uint32_t a1 = f2tf32(F1[kglob + ks + tig]);
            uint32_t a2 = f2tf32(F0[kglob + ks + tig + 4]);
            uint32_t a3 = f2tf32(F1[kglob + ks + tig + 4]);
#pragma unroll
            for (int nt = 0; nt < 4; ++nt) {
                uint32_t b0 = sw[(ks + tig) * SW_STRIDE + cbase + nt * 8 + g];
                uint32_t b1 = sw[(ks + tig + 4) * SW_STRIDE + cbase + nt * 8 + g];
                asm("mma.sync.aligned.m16n8k8.row.col.f32.tf32.tf32.f32 "
                    "{%0,%1,%2,%3}, {%4,%5,%6,%7}, {%8,%9}, {%0,%1,%2,%3};"
                    : "+f"(acc[nt][0]), "+f"(acc[nt][1]),
                      "+f"(acc[nt][2]), "+f"(acc[nt][3])
                    : "r"(a0), "r"(a1), "r"(a2), "r"(a3), "r"(b0), "r"(b1));
            }
        }
        __syncthreads();
    }

    if (r0 < nrows) {
        float* dst = g_support + (size_t)r0 * ODIM + cbase;
#pragma unroll
        for (int nt = 0; nt < 4; ++nt)
            *reinterpret_cast<float2*>(dst + nt * 8 + tig * 2) =
                make_float2(acc[nt][0], acc[nt][1]);
    }
    if (r1 < nrows) {
        float* dst = g_support + (size_t)r1 * ODIM + cbase;
#pragma unroll
        for (int nt = 0; nt < 4; ++nt)
            *reinterpret_cast<float2*>(dst + nt * 8 + tig * 2) =
                make_float2(acc[nt][2], acc[nt][3]);
    }
}

// ---------------------------------------------------------------------------
// Histogram of destination rows (g_count zeroed by csr_spmm tail / zero-init).
// ---------------------------------------------------------------------------
__global__ void histogram_kernel(const int* __restrict__ erow, int E) {
    int e = blockIdx.x * blockDim.x + threadIdx.x;
    if (e < E) atomicAdd(&g_count[erow[e]], 1);
}

// ---------------------------------------------------------------------------
// Single-kernel exclusive scan (decoupled lookback over <=64 blocks).
// RACE-FIXED: separate lsum[] for lookback partials + barrier before reuse.
// ---------------------------------------------------------------------------
__global__ __launch_bounds__(SCAN_BLK) void scan_lookback(int n, int nblocks) {
    __shared__ int wsum[32];   // block-local warp prefix sums
    __shared__ int lsum[32];   // lookback reduction partials (separate!)
    __shared__ int sbase;
    const int t = threadIdx.x;
    const int bid = blockIdx.x;
    const int i = bid * SCAN_BLK + t;
    int v = (i < n) ? g_count[i] : 0;

    // block-local inclusive scan
    int x = v;
#pragma unroll
    for (int d = 1; d < 32; d <<= 1) {
        int y = __shfl_up_sync(0xFFFFFFFF, x, d);
        if ((t & 31) >= d) x += y;
    }
    if ((t & 31) == 31) wsum[t >> 5] = x;
    __syncthreads();
    if (t < 32) {
        int s = wsum[t];
#pragma unroll
        for (int d = 1; d < 32; d <<= 1) {
            int y = __shfl_up_sync(0xFFFFFFFF, s, d);
            if (t >= d) s += y;
        }
        wsum[t] = s;
    }
    __syncthreads();
    int wbase = (t >= 32) ? wsum[(t >> 5) - 1] : 0;
    int incl = x + wbase;
    int tot = wsum[31];  // block aggregate (read into register)
    __syncthreads();     // ALL wsum reads complete before any later smem reuse

    // publish aggregate
    if (t == 0) {
        g_aggr[bid] = tot;
        __threadfence();
        g_flag[bid] = 1;
    }

    // lookback: thread t (< bid) waits for predecessor block t
    int pred = 0;
    if (t < bid) {
        while (g_flag[t] == 0) { }
        __threadfence();
        pred = g_aggr[t];
    }
#pragma unroll
    for (int d = 16; d > 0; d >>= 1)
        pred += __shfl_down_sync(0xFFFFFFFF, pred, d);
    if ((t & 31) == 0) lsum[t >> 5] = pred;
    __syncthreads();
    if (t == 0) {
        int b = 0;
        // only warps 0..1 can hold nonzero partials (bid <= 63), but sum all
        for (int wId = 0; wId < 32; ++wId) b += lsum[wId];
        sbase = b;
    }
    __syncthreads();
    int base = sbase;

    if (i < n) {
        int off = base + incl - v;  // exclusive
        g_offset[i] = off;
        g_cursor[i] = off;
    }
    if (bid == nblocks - 1 && t == SCAN_BLK - 1) g_offset[n] = base + incl;
}

__global__ void sort_scatter_kernel(const int* __restrict__ erow,
                                    const int* __restrict__ ecol,
                                    const float* __restrict__ ew,
                                    int E) {
    int e = blockIdx.x * blockDim.x + threadIdx.x;
    if (e >= E) return;
    int r = erow[e];
    int pos = atomicAdd(&g_cursor[r], 1);
    g_edges[pos] = make_int2(ecol[e], __float_as_int(ew[e]));
}

// ---------------------------------------------------------------------------
// CSR SpMM + fused zero-init + tanh: warp per destination row.
// Half-warp edge slots, 4-deep unroll (4 independent gathers in flight).
// Tail: re-zero g_count / g_flag for the next invocation (deterministic).
// ---------------------------------------------------------------------------
__global__ __launch_bounds__(256) void csr_spmm_kernel(float* __restrict__ out,
                                                       const int* __restrict__ act,
                                                       int nrows) {
    int wid = (blockIdx.x * blockDim.x + threadIdx.x) >> 5;
    if (wid >= nrows) return;
    const int lane = threadIdx.x & 31;
    const int h = lane >> 4;
    const int j = (lane & 15) * 4;

    const int beg = g_offset[wid];
    const int end = g_offset[wid + 1];

    float4 a0 = make_float4(0.f, 0.f, 0.f, 0.f);
    float4 a1 = make_float4(0.f, 0.f, 0.f, 0.f);
    float4 a2 = make_float4(0.f, 0.f, 0.f, 0.f);
    float4 a3 = make_float4(0.f, 0.f, 0.f, 0.f);

    int e = beg + h;
    for (; e + 6 < end; e += 8) {
        int2 c0 = g_edges[e];
        int2 c1 = g_edges[e + 2];
        int2 c2 = g_edges[e + 4];
        int2 c3 = g_edges[e + 6];
        float4 v0 = *reinterpret_cast<const float4*>(g_support + (size_t)c0.x * ODIM + j);
        float4 v1 = *reinterpret_cast<const float4*>(g_support + (size_t)c1.x * ODIM + j);
        float4 v2 = *reinterpret_cast<const float4*>(g_support + (size_t)c2.x * ODIM + j);
        float4 v3 = *reinterpret_cast<const float4*>(g_support + (size_t)c3.x * ODIM + j);
        float w0 = __int_as_float(c0.y);
        float w1 = __int_as_float(c1.y);
        float w2 = __int_as_float(c2.y);
        float w3 = __int_as_float(c3.y);
        a0.x += v0.x * w0; a0.y += v0.y * w0; a0.z += v0.z * w0; a0.w += v0.w * w0;
        a1.x += v1.x * w1; a1.y += v1.y * w1; a1.z += v1.z * w1; a1.w += v1.w * w1;
        a2.x += v2.x * w2; a2.y += v2.y * w2; a2.z += v2.z * w2; a2.w += v2.w * w2;
        a3.x += v3.x * w3; a3.y += v3.y * w3; a3.z += v3.z * w3; a3.w += v3.w * w3;
    }
    for (; e < end; e += 2) {
        int2 cw = g_edges[e];
        float w = __int_as_float(cw.y);
        float4 v = *reinterpret_cast<const float4*>(g_support + (size_t)cw.x * ODIM + j);
        a0.x += v.x * w; a0.y += v.y * w; a0.z += v.z * w; a0.w += v.w * w;
    }
    a0.x += a1.x + a2.x + a3.x;
    a0.y += a1.y + a2.y + a3.y;
    a0.z += a1.z + a2.z + a3.z;
    a0.w += a1.w + a2.w + a3.w;

    a0.x += __shfl_down_sync(0xFFFFFFFF, a0.x, 16);
    a0.y += __shfl_down_sync(0xFFFFFFFF, a0.y, 16);
    a0.z += __shfl_down_sync(0xFFFFFFFF, a0.z, 16);
    a0.w += __shfl_down_sync(0xFFFFFFFF, a0.w, 16);

    if (h == 0) {
        if (*act) {
            a0.x = tanhf(a0.x);
            a0.y = tanhf(a0.y);
            a0.z = tanhf(a0.z);
            a0.w = tanhf(a0.w);
        }
        *reinterpret_cast<float4*>(out + (size_t)wid * ODIM + j) = a0;
    }

    // scratch hygiene for the next invocation (same work every call)
    if (lane == 0) g_count[wid] = 0;
    if (lane == 1 && wid < MAX_SCAN_BLOCKS) g_flag[wid] = 0;
}

extern "C" void kernel_launch(void* const* d_in, const int* in_sizes, int n_in,
                              void* d_out, int out_size) {
    const float* F   = (const float*)d_in[0];
    const float* W   = (const float*)d_in[1];
    const int*   er  = (const int*)d_in[2];
    const int*   ec  = (const int*)d_in[3];
    const float* ew  = (const float*)d_in[4];
    const int*   act = (const int*)d_in[5];

    int nrows = in_sizes[0] / KDIM;
    int E = in_sizes[2];
    float* out = (float*)d_out;

    // One-time infra (first call is the non-captured correctness run).
    static cudaStream_t s2 = nullptr;
    static cudaEvent_t evFork = nullptr, evJoin = nullptr;
    if (s2 == nullptr) {
        cudaStreamCreateWithFlags(&s2, cudaStreamNonBlocking);
        cudaEventCreateWithFlags(&evFork, cudaEventDisableTiming);
        cudaEventCreateWithFlags(&evJoin, cudaEventDisableTiming);
    }

    // Fork: branch B (edge sort) on s2, branch A (GEMM) on stream 0.
    cudaEventRecord(evFork, 0);
    cudaStreamWaitEvent(s2, evFork, 0);

    // Branch B: counting sort of edges by destination row.
    int nsb = (nrows + SCAN_BLK - 1) / SCAN_BLK;  // <= 64
    histogram_kernel<<<(E + 255) / 256, 256, 0, s2>>>(er, E);
    scan_lookback<<<nsb, SCAN_BLK, 0, s2>>>(nrows, nsb);
    sort_scatter_kernel<<<(E + 255) / 256, 256, 0, s2>>>(er, ec, ew, E);

    // Branch A: dense projection (tf32 tensor cores).
    gnn_gemm_tf32<<<(nrows + 127) / 128, 512>>>(F, W, nrows);

    // Join.
    cudaEventRecord(evJoin, s2);
    cudaStreamWaitEvent(0, evJoin, 0);

    // CSR SpMM with fused zero-init + tanh (warp per row) + scratch re-zero.
    int blocks = (nrows * 32 + 255) / 256;
    csr_spmm_kernel<<<blocks, 256>>>(out, act, nrows);
}